// round 17
// baseline (speedup 1.0000x reference)
#include <cuda_runtime.h>
#include <cuda_fp16.h>
#include <cstdint>

#define SEQ   512
#define BATCH 4
#define NROWS (BATCH * SEQ)
#define DEMB  768
#define DCAT  784
#define KPAD  832             // 13 chunks of 64 halves
#define KCHUNKS 13
#define VOCAB 50265
#define NPAD  50432           // 394 * 128
#define MSZ   (BATCH * SEQ * SEQ)

#define ACH 8192
#define BCH 8192
#define PGRID 256
#define NTILES_M 16
#define NTILES_N (NPAD / 128)             // 394
#define TOTAL_TILES (NTILES_M * NTILES_N) // 6304
#define GPERS 296                          // 2 CTAs/SM * 148

__device__ float  g_M1 [MSZ];
__device__ float  g_M2 [MSZ];
__device__ float  g_M3 [MSZ];
__device__ float  g_M4 [MSZ];
__device__ float  g_M8 [MSZ];
__device__ float  g_M12[MSZ];
__device__ __half g_xh[(size_t)(NROWS / 128) * KCHUNKS * ACH];
__device__ __half g_wt[(size_t)(NPAD / 128) * KCHUNKS * BCH];
__device__ int    g_mask_flags;
__device__ unsigned g_epoch  = 0;
__device__ unsigned g_bcount = 0;

// ================= helpers =================
__device__ __forceinline__ uint32_t smem_u32(const void* p) {
    uint32_t a;
    asm("{ .reg .u64 t; cvta.to.shared.u64 t, %1; cvt.u32.u64 %0, t; }"
        : "=r"(a) : "l"(p));
    return a;
}
__device__ __host__ __forceinline__ uint32_t swz_half(int r, int kh) {
    return (uint32_t)(r * 64 + ((((kh >> 3) ^ r) & 7) << 3) + (kh & 7));
}
__device__ __forceinline__ void mbar_init(uint32_t a, uint32_t cnt) {
    asm volatile("mbarrier.init.shared.b64 [%0], %1;" :: "r"(a), "r"(cnt) : "memory");
}
__device__ __forceinline__ void mbar_expect_tx(uint32_t a, uint32_t bytes) {
    asm volatile("mbarrier.arrive.expect_tx.shared.b64 _, [%0], %1;"
                 :: "r"(a), "r"(bytes) : "memory");
}
__device__ __forceinline__ void mbar_arrive(uint32_t a) {
    asm volatile("mbarrier.arrive.shared.b64 _, [%0];" :: "r"(a) : "memory");
}
__device__ __forceinline__ void bulk_g2s(uint32_t dst, const void* src,
                                         uint32_t bytes, uint32_t mbar) {
    asm volatile(
        "cp.async.bulk.shared::cluster.global.mbarrier::complete_tx::bytes "
        "[%0], [%1], %2, [%3];"
        :: "r"(dst), "l"(src), "r"(bytes), "r"(mbar) : "memory");
}
__device__ __forceinline__ void mbar_wait(uint32_t a, uint32_t ph) {
    uint32_t done;
    asm volatile(
        "{\n\t.reg .pred p;\n\t"
        "mbarrier.try_wait.parity.acquire.cta.shared::cta.b64 p, [%1], %2;\n\t"
        "selp.b32 %0, 1, 0, p;\n\t}"
        : "=r"(done) : "r"(a), "r"(ph) : "memory");
    if (!done) {
        asm volatile(
            "{\n\t.reg .pred P1;\n\t"
            "WL_%=:\n\t"
            "mbarrier.try_wait.parity.acquire.cta.shared::cta.b64 P1, [%0], %1, 0x989680;\n\t"
            "@P1 bra.uni WD_%=;\n\t"
            "bra.uni WL_%=;\n\t"
            "WD_%=:\n\t}"
            :: "r"(a), "r"(ph) : "memory");
    }
}
// grid barrier: epoch-based, replay-deterministic
__device__ __forceinline__ void gsync(unsigned base, int k) {
    __syncthreads();
    if (threadIdx.x == 0) {
        __threadfence();
        unsigned arrived = atomicAdd(&g_bcount, 1u);
        if (arrived == PGRID - 1) {
            g_bcount = 0;
            __threadfence();
            *(volatile unsigned*)&g_epoch = base + (unsigned)k;
        } else {
            while (*(volatile unsigned*)&g_epoch < base + (unsigned)k) __nanosleep(64);
        }
        __threadfence();
    }
    __syncthreads();
}

// ================= mask dtype detection =================
__global__ void reset_flags_kernel() { g_mask_flags = 0; }

__global__ __launch_bounds__(256) void detect_mask_kernel(
    const uint4* __restrict__ p, int nvec)
{
    int fl = 0;
    for (int i = blockIdx.x * blockDim.x + threadIdx.x; i < nvec;
         i += gridDim.x * blockDim.x) {
        uint4 v = p[i];
        uint32_t any = v.x | v.y | v.z | v.w;
        if (any & 0xFEFEFEFEu) fl |= 2;
        else if (any & 0x01010100u) fl |= 1;
    }
    if (fl) atomicOr(&g_mask_flags, fl);
}

__device__ __forceinline__ int mask_fmt() {
    int f = g_mask_flags;
    return (f & 2) ? 2 : ((f & 1) ? 1 : 0);
}
__device__ __forceinline__ bool mask_at(const void* m, int fmt, long idx) {
    if (fmt == 0) return ((const int*)m)[idx] != 0;
    if (fmt == 1) return ((const unsigned char*)m)[idx] != 0;
    return ((const float*)m)[idx] != 0.0f;
}

// ================= W -> chunked swizzled fp16 =================
__global__ __launch_bounds__(256) void convert_w_kernel(
    const float* __restrict__ W, __half* __restrict__ Wt)
{
    __shared__ float t[32][33];
    int n0 = blockIdx.x * 32, k0 = blockIdx.y * 32;
    int tx = threadIdx.x & 31, ty = threadIdx.x >> 5;
    #pragma unroll
    for (int i = 0; i < 32; i += 8) {
        int k = k0 + ty + i, n = n0 + tx;
        t[ty + i][tx] = (k < DCAT && n < VOCAB) ? W[(size_t)k * VOCAB + n] : 0.0f;
    }
    __syncthreads();
    #pragma unroll
    for (int i = 0; i < 32; i += 8) {
        int n = n0 + ty + i, k = k0 + tx;
        int ntile = n >> 7, rr = n & 127;
        int kc = k >> 6, kh = k & 63;
        size_t base = ((size_t)ntile * KCHUNKS + kc) * BCH;
        Wt[base + swz_half(rr, kh)] = __float2half_rn(t[tx][ty + i]);
    }
}

// ================= embedding gather + node average -> swizzled fp16 xh =================
__global__ __launch_bounds__(256) void embed_kernel(
    const int* __restrict__ code, const int* __restrict__ pos,
    const void* __restrict__ mask, const float* __restrict__ table,
    __half* __restrict__ xh)
{
    int row = blockIdx.x;
    int b = row >> 9;
    int tid = threadIdx.x;
    int mtile = row >> 7, r = row & 127;
    size_t mbase = (size_t)mtile * KCHUNKS * ACH;

    float v0, v1, v2;
    if (pos[row] != 0) {
        long co = (long)code[row] * DEMB;
        v0 = table[co + tid];
        v1 = table[co + tid + 256];
        v2 = table[co + tid + 512];
    } else {
        __shared__ int list[SEQ];
        __shared__ int cnt;
        if (tid == 0) cnt = 0;
        __syncthreads();
        int fmt = mask_fmt();
        for (int j = tid; j < SEQ; j += 256) {
            bool f = (pos[(b << 9) + j] >= 2) && mask_at(mask, fmt, (long)row * SEQ + j);
            if (f) { int k = atomicAdd(&cnt, 1); list[k] = code[(b << 9) + j]; }
        }
        __syncthreads();
        int n = cnt;
        float inv = 1.0f / ((float)n + 1e-10f);
        float a0 = 0.f, a1 = 0.f, a2 = 0.f;
        int jj = 0;
        for (; jj + 4 <= n; jj += 4) {
            const float* e0 = table + (long)list[jj] * DEMB;
            const float* e1 = table + (long)list[jj + 1] * DEMB;
            const float* e2 = table + (long)list[jj + 2] * DEMB;
            const float* e3 = table + (long)list[jj + 3] * DEMB;
            a0 += e0[tid] + e1[tid] + e2[tid] + e3[tid];
            a1 += e0[tid + 256] + e1[tid + 256] + e2[tid + 256] + e3[tid + 256];
            a2 += e0[tid + 512] + e1[tid + 512] + e2[tid + 512] + e3[tid + 512];
        }
        for (; jj < n; jj++) {
            const float* e0 = table + (long)list[jj] * DEMB;
            a0 += e0[tid]; a1 += e0[tid + 256]; a2 += e0[tid + 512];
        }
        v0 = a0 * inv; v1 = a1 * inv; v2 = a2 * inv;
    }
    float vals[3] = {v0, v1, v2};
    #pragma unroll
    for (int l = 0; l < 3; l++) {
        int d = tid + l * 256;
        int kc = d >> 6, kh = d & 63;
        xh[mbase + (size_t)kc * ACH + swz_half(r, kh)] = __float2half_rn(vals[l]);
    }
}

__device__ __forceinline__ uint32_t f2tf32(float f) {
    uint32_t u;
    asm("cvt.rna.tf32.f32 %0, %1;" : "=r"(u) : "f"(f));
    return u;
}

// ================= power-chain bodies =================
#define SM_FLOATS 6912

__device__ void build_m_body(const void* mask, float* __restrict__ M1,
                             int row, float* red)
{
    int i = row & (SEQ - 1);
    int tid = threadIdx.x, lane = tid & 31, warp = tid >> 5;
    int fmt = mask_fmt();
    long base = (long)row * SEQ;

    float s = 0.f;
    for (int j = tid; j < SEQ; j += 256)
        s += (j == i) ? 1.0f : (mask_at(mask, fmt, base + j) ? 1.0f : 0.0f);
    #pragma unroll
    for (int off = 16; off > 0; off >>= 1) s += __shfl_down_sync(0xffffffffu, s, off);
    if (lane == 0) red[warp] = s;
    __syncthreads();
    float tot = red[0] + red[1] + red[2] + red[3] + red[4] + red[5] + red[6] + red[7];
    float inv = 1.0f / tot;
    for (int j = tid; j < SEQ; j += 256) {
        float a = (j == i) ? 1.0f : (mask_at(mask, fmt, base + j) ? 1.0f : 0.0f);
        M1[base + j] = a * inv;
    }
    __syncthreads();
}

__device__ void gemm64_body(const float* __restrict__ A, const float* __restrict__ B,
                            float* __restrict__ C, int m0, int n0,
                            float* As, float* Bs)
{
    const int tid = threadIdx.x;
    const int lane = tid & 31, warp = tid >> 5;
    const int wm = (warp >> 2) * 32;
    const int wn = (warp & 3) * 32;
    const int g = lane >> 2, t4 = lane & 3;

    float acc[2][4][4];
    #pragma unroll
    for (int a = 0; a < 2; a++)
        #pragma unroll
        for (int bq = 0; bq < 4; bq++)
            #pragma unroll
            for (int c = 0; c < 4; c++) acc[a][bq][c] = 0.f;

    const int KT = SEQ >> 4;
    float4 ra;
    float  rb[8];

    auto ldg_tiles = [&](int kt) {
        {
            int ar = tid >> 2, ak = (tid & 3) << 2;
            ra = *reinterpret_cast<const float4*>(
                A + (size_t)(m0 + ar) * SEQ + (kt * 16 + ak));
        }
        #pragma unroll
        for (int l = 0; l < 8; l++) {
            int idx = tid + l * 256;
            rb[l] = B[(size_t)(kt * 16 + (idx >> 7)) * SEQ + n0 + (idx & 127)];
        }
    };
    auto sts_tiles = [&](int buf) {
        {
            int ar = tid >> 2, ak = (tid & 3) << 2;
            float* dst = As + buf * 1280 + ar * 20 + ak;
            dst[0] = __uint_as_float(f2tf32(ra.x));
            dst[1] = __uint_as_float(f2tf32(ra.y));
            dst[2] = __uint_as_float(f2tf32(ra.z));
            dst[3] = __uint_as_float(f2tf32(ra.w));
        }
        #pragma unroll
        for (int l = 0; l < 8; l++) {
            int idx = tid + l * 256;
            Bs[buf * 2176 + (idx >> 7) * 136 + (idx & 127)] =
                __uint_as_float(f2tf32(rb[l]));
        }
    };
    auto compute = [&](int buf) {
        #pragma unroll
        for (int ks = 0; ks < 2; ks++) {
            uint32_t af[2][4];
            int k = ks * 8 + t4;
            #pragma unroll
            for (int tm = 0; tm < 2; tm++) {
                int r = wm + tm * 16 + g;
                const float* a0 = As + buf * 1280;
                af[tm][0] = __float_as_uint(a0[r * 20 + k]);
                af[tm][1] = __float_as_uint(a0[(r + 8) * 20 + k]);
                af[tm][2] = __float_as_uint(a0[r * 20 + k + 4]);
                af[tm][3] = __float_as_uint(a0[(r + 8) * 20 + k + 4]);
            }
            uint32_t bf[4][2];
            #pragma unroll
            for (int tn = 0; tn < 4; tn++) {
                int c = wn + tn * 8 + g;
                const float* b0 = Bs + buf * 2176;
                bf[tn][0] = __float_as_uint(b0[k * 136 + c]);
                bf[tn][1] = __float_as_uint(b0[(k + 4) * 136 + c]);
            }
            #pragma unroll
            for (int tm = 0; tm < 2; tm++)
                #pragma unroll
                for (int tn = 0; tn < 4; tn++)
                    asm volatile(
                        "mma.sync.aligned.m16n8k8.row.col.f32.tf32.tf32.f32 "
                        "{%0,%1,%2,%3}, {%4,%5,%6,%7}, {%8,%9}, {%0,%1,%2,%3};\n"
                        : "+f"(acc[tm][tn][0]), "+f"(acc[tm][tn][1]),
                          "+f"(acc[tm][tn][2]), "+f"(acc[tm][tn][3])
                        : "r"(af[tm][0]), "r"(af[tm][1]),
                          "r"(af[tm][2]), "r"(af[tm][3]),
                          "r"(bf[tn][0]), "r"(bf[tn][1]));
        }
    };

    ldg_tiles(0);
    sts_tiles(0);
    __syncthreads();
    for (int kt = 0; kt < KT; kt++) {
        if (kt + 1 < KT) ldg_tiles(kt + 1);
        compute(kt & 1);
        if (kt + 1 < KT) sts_tiles((kt + 1) & 1);
        __syncthreads();
    }

    #pragma unroll
    for (int tm = 0; tm < 2; tm++) {
        int r = m0 + wm + tm * 16 + g;
        #pragma unroll
        for (int tn = 0; tn < 4; tn++) {
            int c = n0 + wn + tn * 8 + (t4 << 1);
            C[(size_t)r * SEQ + c]           = acc[tm][tn][0];
            C[(size_t)r * SEQ + c + 1]       = acc[tm][tn][1];
            C[(size_t)(r + 8) * SEQ + c]     = acc[tm][tn][2];
            C[(size_t)(r + 8) * SEQ + c + 1] = acc[tm][tn][3];
        }
    }
    __syncthreads();
}

__device__ void diag_body(const float* __restrict__ M1, const float* __restrict__ M2,
                          const float* __restrict__ M3, const float* __restrict__ M4,
                          const float* __restrict__ M8, const float* __restrict__ M12,
                          __half* __restrict__ xh, int row, float* sm)
{
    int b = row >> 9, i = row & (SEQ - 1);
    int tid = threadIdx.x, lane = tid & 31, warp = tid >> 5;
    long base = (long)row * SEQ;
    long mbq  = (long)b * SEQ * SEQ;
    int mtile = row >> 7, r = row & 127;
    size_t cbase = ((size_t)mtile * KCHUNKS + 12) * ACH;

    float* rws = sm;
    float* cls = sm + 4 * SEQ;
    float* wred = sm + 7 * SEQ;

    for (int j = tid; j < SEQ; j += 256) {
        rws[0 * SEQ + j] = M1[base + j];
        rws[1 * SEQ + j] = M2[base + j];
        rws[2 * SEQ + j] = M3[base + j];
        rws[3 * SEQ + j] = M4[base + j];
        cls[0 * SEQ + j] = M4 [mbq + (long)j * SEQ + i];
        cls[1 * SEQ + j] = M8 [mbq + (long)j * SEQ + i];
        cls[2 * SEQ + j] = M12[mbq + (long)j * SEQ + i];
    }
    __syncthreads();

    float part[10];
    #pragma unroll
    for (int p = 0; p < 10; p++) part[p] = 0.f;
    for (int j = tid; j < SEQ; j += 256) {
        float a1 = rws[j], a2 = rws[SEQ + j], a3 = rws[2 * SEQ + j], a4 = rws[3 * SEQ + j];
        float c4 = cls[j], c8 = cls[SEQ + j], c12 = cls[2 * SEQ + j];
        part[0] += a1 * c4;   part[1] += a2 * c4;   part[2] += a3 * c4;
        part[3] += a1 * c8;   part[4] += a2 * c8;   part[5] += a3 * c8;
        part[6] += a1 * c12;  part[7] += a2 * c12;  part[8] += a3 * c12;
        part[9] += a4 * c12;
    }
    #pragma unroll
    for (int p = 0; p < 10; p++) {
        float v = part[p];
        #pragma unroll
        for (int off = 16; off > 0; off >>= 1) v += __shfl_down_sync(0xffffffffu, v, off);
        if (lane == 0) wred[p * 8 + warp] = v;
    }
    __syncthreads();

    if (tid < 10) {
        const int slot[10] = {4, 5, 6, 8, 9, 10, 12, 13, 14, 15};
        float v = 0.f;
        #pragma unroll
        for (int w = 0; w < 8; w++) v += wred[tid * 8 + w];
        xh[cbase + swz_half(r, slot[tid])] = __float2half_rn(v);
    }
    if (tid == 0) {
        xh[cbase + swz_half(r, 0)]  = __float2half_rn(rws[i]);
        xh[cbase + swz_half(r, 1)]  = __float2half_rn(rws[SEQ + i]);
        xh[cbase + swz_half(r, 2)]  = __float2half_rn(rws[2 * SEQ + i]);
        xh[cbase + swz_half(r, 3)]  = __float2half_rn(rws[3 * SEQ + i]);
        xh[cbase + swz_half(r, 7)]  = __float2half_rn(cls[SEQ + i]);
        xh[cbase + swz_half(r, 11)] = __float2half_rn(cls[2 * SEQ + i]);
    }
    if (tid >= 16 && tid < 64)
        xh[cbase + swz_half(r, tid)] = __half(0.0f);
    __syncthreads();
}

// ================= fused persistent power chain =================
__global__ __launch_bounds__(256, 2) void power_chain_kernel(
    const void* __restrict__ mask,
    float* __restrict__ M1, float* __restrict__ M2, float* __restrict__ M3,
    float* __restrict__ M4, float* __restrict__ M8, float* __restrict__ M12,
    __half* __restrict__ xh)
{
    __shared__ float sm[SM_FLOATS];
    __shared__ unsigned s_base;
    float* As = sm;
    float* Bs = sm + 2560;
    const long MS = (long)SEQ * SEQ;

    if (threadIdx.x == 0) s_base = *(volatile unsigned*)&g_epoch;
    __syncthreads();
    unsigned base = s_base;

    for (int row = blockIdx.x; row < NROWS; row += PGRID)
        build_m_body(mask, M1, row, sm);
    gsync(base, 1);

    for (int u = blockIdx.x; u < 128; u += PGRID) {
        int b = u >> 5, t = u & 31, mt = t >> 2, nt = t & 3;
        gemm64_body(M1 + b * MS, M1 + b * MS, M2 + b * MS, mt * 64, nt * 128, As, Bs);
    }
    gsync(base, 2);

    for (int u = blockIdx.x; u < 256; u += PGRID) {
        int op = u >> 7, rem = u & 127;
        int b = rem >> 5, t = rem & 31, mt = t >> 2, nt = t & 3;
        const float* Bp = op ? (M2 + b * MS) : (M1 + b * MS);
        float*       Cp = op ? (M4 + b * MS) : (M3 + b * MS);
        gemm64_body(M2 + b * MS, Bp, Cp, mt * 64, nt * 128, As, Bs);
    }
    gsync(base, 3);

    for (int u = blockIdx.x; u < 128; u += PGRID) {
        int b = u >> 5, t = u & 31, mt = t >> 2, nt = t & 3;
        gemm64_body(M4 + b * MS, M4 + b * MS, M8 + b * MS, mt * 64, nt * 128, As, Bs);
    }
    gsync(base, 4);

    for (int u = blockIdx.x; u < 128; u += PGRID) {
        int b = u >> 5, t = u & 31, mt = t >> 2, nt = t & 3;
        gemm64_body(M8 + b * MS, M4 + b * MS, M12 + b * MS, mt * 64, nt * 128, As, Bs);
    }
    gsync(base, 5);

    for (int row = blockIdx.x; row < NROWS; row += PGRID)
        diag_body(M1, M2, M3, M4, M8, M12, xh, row, sm);
}

// ================= final GEMM: persistent fp16 mma + ldmatrix =================
#define STG_BYTES (ACH * 2 + BCH * 2)   // 32768
#define NSTAGE 3
#define FSMEM (NSTAGE * STG_BYTES + 1024)

__global__ __launch_bounds__(256, 2) void gemm_final_fp16(
    const __half* __restrict__ A, const __half* __restrict__ B,
    float* __restrict__ C, const float* __restrict__ bias)
{
    extern __shared__ char dynsm[];
    __shared__ __align__(8) uint64_t s_full[NSTAGE];
    __shared__ __align__(8) uint64_t s_empty[NSTAGE];

    const int bid = blockIdx.x;
    const int tid = threadIdx.x;
    const int lane = tid & 31, warp = tid >> 5;
    const int wm = (warp >> 2) * 64;
    const int wn = (warp & 3) * 32;
    const int g = lane >> 2, t4 = lane & 3;

    uint32_t raw_u = smem_u32(dynsm);
    uint32_t base_u = (raw_u + 1023u) & ~1023u;

    const int nT = (TOTAL_TILES - bid + GPERS - 1) / GPERS;
    const int totq = nT * KCHUNKS;

    uint32_t fullb[NSTAGE], emptyb[NSTAGE];
    #pragma unroll
    for (int s = 0; s < NSTAGE; s++) {
        fullb[s]  = smem_u32(&s_full[s]);
        emptyb[s] = smem_u32(&s_empty[s]);
    }

    if (tid == 0) {
        #pragma unroll
        for (int s = 0; s < NSTAGE; s++) {
            mbar_init(fullb[s], 1);
            mbar_init(emptyb[s], 8);
        }
    }
    __syncthreads();

    auto issue_chunk = [&](int q, int s) {
        int i = q / KCHUNKS, kc = q - i * KCHUNKS;
        int gt = bid + i * GPERS;
        int mt = gt & 15, nt = gt >> 4;
        const __half* pa = A + ((size_t)mt * KCHUNKS + kc) * ACH;
        const __half* pb = B + ((size_t)nt * KCHUNKS + kc) * BCH;
        mbar_expect_tx(fullb[s], STG_BYTES);
        bulk_g2s(base_u + s * STG_BYTES,           pa, ACH * 2, fullb[s]);
        bulk_g2s(base_u + s * STG_BYTES + ACH * 2, pb, BCH * 2, fullb[s]);
    };

    if (tid == 0) {
        #pragma unroll
        for (int s = 0; s < NSTAGE; s++)
            if (s < totq) issue_chunk(s, s);
    }

    float acc[4][4][4];
    #pragma unroll
    for (int a = 0; a < 4; a++)
        #pragma unroll
        for (int b = 0; b < 4; b++)
            #pragma unroll
            for (int c = 0; c < 4; c++) acc[a][b][c] = 0.f;

    int fph[NSTAGE] = {0, 0, 0};
    int eph[NSTAGE] = {0, 0, 0};

    const int lm  = lane >> 3;
    const int l7  = lane & 7;
    const int a_row_off = (lm & 1) * 8 + l7;
    const int a_k_off   = (lm >> 1) * 8;
    const int b_tnl     = lm >> 1;
    const int b_khalf   = lm & 1;

    int kc_cur = 0, tile_i = 0;
    for (int q = 0; q < totq; q++) {
        int s = q % NSTAGE;
        mbar_wait(fullb[s], fph[s]);
        fph[s] ^= 1;

        uint32_t sA_u = base_u + s * STG_BYTES;
        uint32_t sB_u = sA_u + ACH * 2;

        #pragma unroll
        for (int kk = 0; kk < 4; kk++) {
            int k0 = kk * 16;
            uint32_t af[4][4];
            #pragma unroll
            for (int tm = 0; tm < 4; tm++) {
                int row  = wm + tm * 16 + a_row_off;
                int kcol = k0 + a_k_off;
                uint32_t addr = sA_u + swz_half(row, kcol) * 2;
                asm volatile(
                    "ldmatrix.sync.aligned.m8n8.x4.shared.b16 {%0,%1,%2,%3}, [%4];"
                    : "=r"(af[tm][0]), "=r"(af[tm][1]),
                      "=r"(af[tm][2]), "=r"(af[tm][3])
                    : "r"(addr));
            }
            uint32_t bf[4][2];
            #pragma unroll
            for (int half = 0; half < 2; half++) {
                int n    = wn + half * 16 + b_tnl * 8 + l7;
                int kcol = k0 + b_khalf * 8;
                uint32_t addr = sB_u + swz_half(n, kcol) * 2;
                asm volatile(
                    "ldmatrix.sync.aligned.m8n8.x4.shared.b16 {%0,%1,%2,%3}, [%4];"
                    : "=r"(bf[2 * half][0]), "=r"(bf[2 * half][1]),
                      "=r"(bf[2 * half + 1][0]), "=r"(bf[2 * half + 1][1])
                    : "r"(addr));
            }
            #pragma unroll
            for (int tm = 0; tm < 4; tm++)
                #pragma unroll
                for (int tn = 0; tn < 4; tn++)
                    asm volatile(
                        "mma.sync.aligned.m16n8k16.row.col.f32.f16.f16.f32 "
                        "{%0,%1,%2,%3}, {%4,%5,%6,%7}, {%8,%9}, {%0,%1,%2,%3};\n"
                        : "+f"(acc[tm][tn][0]), "+f"(acc[tm][tn][1]),
                          "+f"(acc[tm][tn][2]), "+f"(acc[tm][tn][3])
                        : "r"(af[tm][0]), "r"(af[tm][1]),
                          "r"(af[tm][2]), "r"(af[tm][3]),
                          "r"(bf[tn][0]), "r"(bf[tn][1]));
        }

        __syncwarp();
        if (lane == 0) mbar_arrive(emptyb[s]);

        if (tid == 0) {
            int nq = q + NSTAGE;
            if (nq < totq) {
                mbar_wait(emptyb[s], eph[s]);
                eph[s] ^= 1;
                issue_chunk(nq, s);
            }
        }

        if (++kc_cur == KCHUNKS) {
            // ---- epilogue for tile_i (producer already running ahead) ----
            kc_cur = 0;
            int gt = bid + tile_i * GPERS;
            tile_i++;
            int m0 = (gt & 15) * 128;
            int n0 = (gt >> 4) * 128;
            bool interior = (n0 + 128 <= VOCAB);
            #pragma unroll
            for (int tm = 0; tm < 4; tm++) {
                int r = m0 + wm + tm * 16 + g;
                float* C0 = C + (size_t)r * VOCAB;
                float* C1 = C + (size_t)(r + 8) * VOCAB;
                #pragma unroll
                for (int tn = 0; tn < 4; tn++) {
                    int c = n0 + wn + tn * 8 + (t4 << 1);
                    if (interior) {
                        float b0 = bias[c], b1 = bias[c + 1];
                        C0[c]     = acc[tm][tn][0] + b0;
                        C0[c + 1] = acc[tm][tn][1] + b1;
                        C1[c]     = acc[tm][tn][2] + b0;
                        C1[c + 1] = acc[tm][tn][3] + b1;
                    } else {
                        if (c < VOCAB) {
                            float bv = bias[c];
                            C0[c] = acc[tm][tn][0] + bv;
                            C1[c] = acc[tm][tn][2] + bv;
                        }
                        if (c + 1 < VOCAB) {
                            float bv = bias[c + 1];
                            C0[c + 1] = acc[tm][tn][1] + bv;
                            C1[c + 1] = acc[tm][tn][3] + bv;
                        }
                    }
                    acc[tm][tn][0] = 0.f; acc[tm][tn][1] = 0.f;
                    acc[tm][tn][2] = 0.f; acc[tm][tn][3] = 0.f;
                }
            }
        }
    }
}

extern "C" void kernel_launch(void* const* d_in, const int* in_sizes, int n_in,
                              void* d_out, int out_size)
{
    const int*   code  = (const int*)d_in[0];
    const int*   pos   = (const int*)d_in[1];
    const void*  mask  = d_in[2];
    const float* table = (const float*)d_in[3];
    const float* W     = (const float*)d_in[4];
    const float* bias  = (const float*)d_in[5];
    float* out = (float*)d_out;

    float *pM1, *pM2, *pM3, *pM4, *pM8, *pM12;
    __half *pxh, *pwt;
    cudaGetSymbolAddress((void**)&pM1,  g_M1);
    cudaGetSymbolAddress((void**)&pM2,  g_M2);
    cudaGetSymbolAddress((void**)&pM3,  g_M3);
    cudaGetSymbolAddress((void**)&pM4,  g_M4);
    cudaGetSymbolAddress((void**)&pM8,  g_M8);
    cudaGetSymbolAddress((void**)&pM12, g_M12);
    cudaGetSymbolAddress((void**)&pxh,  g_xh);
    cudaGetSymbolAddress((void**)&pwt,  g_wt);

    static cudaStream_t s_side = nullptr;
    static cudaEvent_t  ev_fork = nullptr, ev_det = nullptr, ev_side = nullptr;
    if (!s_side) {
        cudaStreamCreateWithFlags(&s_side, cudaStreamNonBlocking);
        cudaEventCreateWithFlags(&ev_fork, cudaEventDisableTiming);
        cudaEventCreateWithFlags(&ev_det,  cudaEventDisableTiming);
        cudaEventCreateWithFlags(&ev_side, cudaEventDisableTiming);
        cudaFuncSetAttribute(gemm_final_fp16,
                             cudaFuncAttributeMaxDynamicSharedMemorySize, FSMEM);
    }

    cudaEventRecord(ev_fork, 0);
    cudaStreamWaitEvent(s_side, ev_fork, 0);
    dim3 gW(NPAD / 32, (KPAD + 31) / 32);
    convert_w_kernel<<<gW, 256, 0, s_side>>>(W, pwt);

    reset_flags_kernel<<<1, 1>>>();
    detect_mask_kernel<<<64, 256>>>((const uint4*)mask, in_sizes[2] / 16);
    cudaEventRecord(ev_det, 0);

    cudaStreamWaitEvent(s_side, ev_det, 0);
    embed_kernel<<<NROWS, 256, 0, s_side>>>(code, pos, mask, table, pxh);
    cudaEventRecord(ev_side, s_side);

    power_chain_kernel<<<PGRID, 256>>>(mask, pM1, pM2, pM3, pM4, pM8, pM12, pxh);

    cudaStreamWaitEvent(0, ev_side, 0);

    gemm_final_fp16<<<GPERS, 256, FSMEM>>>(pxh, pwt, out, bias);
}